// round 2
// baseline (speedup 1.0000x reference)
#include <cuda_runtime.h>
#include <cuda_bf16.h>
#include <math.h>

#define NQ   16384
#define NF   8192
#define DD   64
#define TOPK 32
#define KNN  5

#define BM 128
#define BN 128
#define PADQ 129
#define SMEM_BYTES (2 * 64 * PADQ * 4)   // 66048 bytes

// ---------------- scratch (__device__ globals; no runtime allocation) -------
__device__ float g_Xc[(size_t)NQ * DD];
__device__ float g_Fc[(size_t)NF * DD];
__device__ float g_SqX[NQ];
__device__ float g_SqF[NF];
__device__ unsigned long long g_qbits[NQ];
__device__ unsigned long long g_fbits[NF];
__device__ float g_key[(size_t)NQ * NF];      // 512 MB distance-key matrix
__device__ int   g_topIdx[(size_t)NQ * TOPK];
__device__ float g_colmean[DD];

__device__ __forceinline__ float f_inf() { return __int_as_float(0x7f800000); }

// ---------------- prep: clean values, observed bitmask, sum of squares ------
__global__ void prep_kernel(const float* __restrict__ src, int nrows, int isX)
{
    int w    = (blockIdx.x * blockDim.x + threadIdx.x) >> 5;
    int lane = threadIdx.x & 31;
    if (w >= nrows) return;

    float* clean             = isX ? g_Xc : g_Fc;
    float* sq                = isX ? g_SqX : g_SqF;
    unsigned long long* bits = isX ? g_qbits : g_fbits;

    const float* row = src + (size_t)w * DD;
    float v0 = row[lane];
    float v1 = row[lane + 32];
    bool  o0 = !isnan(v0);
    bool  o1 = !isnan(v1);
    float c0 = o0 ? v0 : 0.0f;
    float c1 = o1 ? v1 : 0.0f;
    clean[(size_t)w * DD + lane]      = c0;
    clean[(size_t)w * DD + lane + 32] = c1;

    unsigned ob0 = __ballot_sync(0xffffffffu, o0);   // observed, features 0..31
    unsigned ob1 = __ballot_sync(0xffffffffu, o1);   // observed, features 32..63

    float s = c0 * c0 + c1 * c1;
    #pragma unroll
    for (int o = 16; o > 0; o >>= 1) s += __shfl_xor_sync(0xffffffffu, s, o);

    if (lane == 0) {
        bits[w] = (unsigned long long)ob0 | ((unsigned long long)ob1 << 32);
        sq[w]   = s;
    }
}

// ---------------- per-column mean of observed fit values (fallback) ---------
__global__ void colmean_kernel(const float* __restrict__ fit)
{
    int c   = blockIdx.x;
    int tid = threadIdx.x;
    float s = 0.0f;
    int   n = 0;
    for (int r = tid; r < NF; r += 256) {
        float v = fit[(size_t)r * DD + c];
        if (!isnan(v)) { s += v; n++; }
    }
    __shared__ float ss[256];
    __shared__ int   sn[256];
    ss[tid] = s; sn[tid] = n;
    __syncthreads();
    for (int o = 128; o > 0; o >>= 1) {
        if (tid < o) { ss[tid] += ss[tid + o]; sn[tid] += sn[tid + o]; }
        __syncthreads();
    }
    if (tid == 0) g_colmean[c] = (sn[0] > 0) ? ss[0] / (float)sn[0] : 0.0f;
}

// ---------------- distance-key kernel: GEMM + sparse mask corrections -------
// key[q][r] = max(SqX+SqF-2*s - corrB - corrC, 0) * 64/cnt ; +inf if cnt==0
__global__ __launch_bounds__(256) void dist_kernel()
{
    extern __shared__ float sm[];
    float* Xs = sm;                 // [64][PADQ]  feature-major query tile
    float* Ys = sm + 64 * PADQ;     // [64][PADQ]  feature-major fit tile

    int tid = threadIdx.x;
    int tx = tid & 15;              // fit-col group
    int ty = tid >> 4;              // query-row group
    int qbase = blockIdx.y * BM;
    int rbase = blockIdx.x * BN;

    // stage tiles (transpose to feature-major); coalesced reads,
    // conflict-free writes (stride 129 -> bank (f+q)%32, f consecutive)
    for (int e = tid; e < BM * DD; e += 256) {
        int q = e >> 6;
        int f = e & 63;
        Xs[f * PADQ + q] = g_Xc[(size_t)(qbase + q) * DD + f];
        Ys[f * PADQ + q] = g_Fc[(size_t)(rbase + q) * DD + f];
    }
    __syncthreads();

    float acc[8][8];
    #pragma unroll
    for (int i = 0; i < 8; i++)
        #pragma unroll
        for (int j = 0; j < 8; j++) acc[i][j] = 0.0f;

    // main dot product s = sum xc*yc
    #pragma unroll 8
    for (int f = 0; f < DD; f++) {
        float xv[8], yv[8];
        #pragma unroll
        for (int i = 0; i < 8; i++) xv[i] = Xs[f * PADQ + ty + 16 * i];
        #pragma unroll
        for (int j = 0; j < 8; j++) yv[j] = Ys[f * PADQ + tx + 16 * j];
        #pragma unroll
        for (int i = 0; i < 8; i++)
            #pragma unroll
            for (int j = 0; j < 8; j++)
                acc[i][j] = fmaf(xv[i], yv[j], acc[i][j]);
    }

    // transform to d2 = SqX + SqF - 2*s
    {
        float sqx[8], sqf[8];
        #pragma unroll
        for (int i = 0; i < 8; i++) sqx[i] = g_SqX[qbase + ty + 16 * i];
        #pragma unroll
        for (int j = 0; j < 8; j++) sqf[j] = g_SqF[rbase + tx + 16 * j];
        #pragma unroll
        for (int i = 0; i < 8; i++)
            #pragma unroll
            for (int j = 0; j < 8; j++)
                acc[i][j] = sqx[i] + sqf[j] - 2.0f * acc[i][j];
    }

    unsigned long long qb[8], fb[8];
    #pragma unroll
    for (int i = 0; i < 8; i++) qb[i] = g_qbits[qbase + ty + 16 * i];
    #pragma unroll
    for (int j = 0; j < 8; j++) fb[j] = g_fbits[rbase + tx + 16 * j];

    // correction B: subtract x^2 at fit-row-missing features
    #pragma unroll
    for (int j = 0; j < 8; j++) {
        unsigned long long mm = ~fb[j];
        while (mm) {
            int f = __ffsll((long long)mm) - 1;
            mm &= mm - 1;
            #pragma unroll
            for (int i = 0; i < 8; i++) {
                float x = Xs[f * PADQ + ty + 16 * i];
                acc[i][j] = fmaf(-x, x, acc[i][j]);
            }
        }
    }
    // correction C: subtract y^2 at query-row-missing features
    #pragma unroll
    for (int i = 0; i < 8; i++) {
        unsigned long long mm = ~qb[i];
        while (mm) {
            int f = __ffsll((long long)mm) - 1;
            mm &= mm - 1;
            #pragma unroll
            for (int j = 0; j < 8; j++) {
                float y = Ys[f * PADQ + tx + 16 * j];
                acc[i][j] = fmaf(-y, y, acc[i][j]);
            }
        }
    }

    // finalize + store
    #pragma unroll
    for (int i = 0; i < 8; i++) {
        size_t rowoff = (size_t)(qbase + ty + 16 * i) * NF + rbase;
        #pragma unroll
        for (int j = 0; j < 8; j++) {
            int n = __popcll(qb[i] & fb[j]);
            float d2 = fmaxf(acc[i][j], 0.0f);
            float k = (n > 0) ? d2 * (64.0f / (float)n) : f_inf();
            g_key[rowoff + tx + 16 * j] = k;
        }
    }
}

// ---------------- top-32 per query ------------------------------------------
__global__ __launch_bounds__(256) void topk_kernel()
{
    int q = blockIdx.x;
    const float* row = g_key + (size_t)q * NF;
    int tid  = threadIdx.x;
    int lane = tid & 31;
    int w    = tid >> 5;

    // per-thread sorted (ascending) top-8 over 32 strided candidates;
    // keys are nonneg floats or +inf -> compare as unsigned bit patterns
    unsigned bd[8];
    int      bi[8];
    #pragma unroll
    for (int j = 0; j < 8; j++) { bd[j] = 0xFFFFFFFFu; bi[j] = -1; }

    #pragma unroll 4
    for (int k = 0; k < NF / 256; k++) {
        int r = tid + (k << 8);
        unsigned v = __float_as_uint(row[r]);
        if (v < bd[7]) {
            bd[7] = v; bi[7] = r;
            #pragma unroll
            for (int j = 7; j > 0; --j) {
                if (bd[j] < bd[j - 1]) {
                    unsigned tv = bd[j]; bd[j] = bd[j - 1]; bd[j - 1] = tv;
                    int      ti = bi[j]; bi[j] = bi[j - 1]; bi[j - 1] = ti;
                }
            }
        }
    }

    // warp-level merge to warp top-32 (32 rounds of head-extraction)
    __shared__ unsigned sv[8 * 32];
    __shared__ int      si[8 * 32];
    {
        int ptr = 0;
        unsigned head = bd[0];
        for (int r = 0; r < 32; r++) {
            unsigned m   = __reduce_min_sync(0xffffffffu, head);
            unsigned bal = __ballot_sync(0xffffffffu, head == m);
            int leader   = __ffs(bal) - 1;
            if (lane == leader) {
                sv[w * 32 + r] = m;
                si[w * 32 + r] = bi[ptr];
                ptr++;
                head = (ptr < 8) ? bd[ptr] : 0xFFFFFFFFu;
            }
        }
    }
    __syncthreads();

    // final merge: warp 0 merges 8 sorted lists of 32 (as 32 sorted runs of 8)
    if (w == 0) {
        unsigned cd[8];
        int      ci[8];
        int src = (lane & 7) * 32 + (lane >> 3) * 8;
        #pragma unroll
        for (int j = 0; j < 8; j++) { cd[j] = sv[src + j]; ci[j] = si[src + j]; }
        int ptr = 0;
        unsigned head = cd[0];
        for (int r = 0; r < 32; r++) {
            unsigned m   = __reduce_min_sync(0xffffffffu, head);
            unsigned bal = __ballot_sync(0xffffffffu, head == m);
            int leader   = __ffs(bal) - 1;
            if (lane == leader) {
                // +inf (cnt==0) entries are invalid donors
                g_topIdx[(size_t)q * TOPK + r] = (m < 0x7f800000u) ? ci[ptr] : -1;
                ptr++;
                head = (ptr < 8) ? cd[ptr] : 0xFFFFFFFFu;
            }
        }
    }
}

// ---------------- impute: warp per query, 2 features per lane ---------------
__global__ void impute_kernel(const float* __restrict__ X, float* __restrict__ out)
{
    int q    = blockIdx.x * (blockDim.x >> 5) + (threadIdx.x >> 5);
    int lane = threadIdx.x & 31;
    if (q >= NQ) return;

    int myidx = g_topIdx[(size_t)q * TOPK + lane];

    float v0 = X[(size_t)q * DD + lane];
    float v1 = X[(size_t)q * DD + lane + 32];
    bool  n0 = isnan(v0);
    bool  n1 = isnan(v1);
    float s0 = 0.0f, s1 = 0.0f;
    int   c0 = 0, c1 = 0;

    for (int r = 0; r < TOPK; r++) {
        int i = __shfl_sync(0xffffffffu, myidx, r);
        if (i < 0) break;                                  // uniform
        unsigned long long fb = g_fbits[i];                // broadcast load
        if (n0 && c0 < KNN && ((fb >> lane) & 1ull)) {
            s0 += g_Fc[(size_t)i * DD + lane]; c0++;
        }
        if (n1 && c1 < KNN && ((fb >> (lane + 32)) & 1ull)) {
            s1 += g_Fc[(size_t)i * DD + lane + 32]; c1++;
        }
        bool done = (!n0 || c0 >= KNN) && (!n1 || c1 >= KNN);
        if (__all_sync(0xffffffffu, done)) break;
    }

    out[(size_t)q * DD + lane]      = n0 ? (c0 ? s0 / (float)c0 : g_colmean[lane])      : v0;
    out[(size_t)q * DD + lane + 32] = n1 ? (c1 ? s1 / (float)c1 : g_colmean[lane + 32]) : v1;
}

// ---------------- launcher ---------------------------------------------------
extern "C" void kernel_launch(void* const* d_in, const int* in_sizes, int n_in,
                              void* d_out, int out_size)
{
    const float* X   = (const float*)d_in[0];
    const float* fit = (const float*)d_in[1];
    float* out = (float*)d_out;
    (void)in_sizes; (void)n_in; (void)out_size;

    cudaFuncSetAttribute(dist_kernel,
                         cudaFuncAttributeMaxDynamicSharedMemorySize, SMEM_BYTES);

    prep_kernel<<<NQ / 8, 256>>>(X, NQ, 1);
    prep_kernel<<<NF / 8, 256>>>(fit, NF, 0);
    colmean_kernel<<<DD, 256>>>(fit);

    dim3 dgrid(NF / BN, NQ / BM);
    dist_kernel<<<dgrid, 256, SMEM_BYTES>>>();

    topk_kernel<<<NQ, 256>>>();

    impute_kernel<<<NQ / 8, 256>>>(X, out);
}